// round 3
// baseline (speedup 1.0000x reference)
#include <cuda_runtime.h>
#include <math.h>
#include <float.h>

#define B_SZ 256
#define D0 50176
#define D1 1024
#define D2 128
#define BM 128
#define BN 128
#define BK 32
#define NT 256
#define S1 28
#define S2 112
#define KT0 56
#define S0_TOT (S1 + S2)
#define S3 8
#define KT3 4
#define S4 16
#define KT4 8
#define SL1_TOT (S3 + S4)

__device__ float    g_part0[(size_t)S0_TOT * B_SZ * D1];
__device__ float    g_part1[(size_t)SL1_TOT * B_SZ * D2];
__device__ float    g_h0[B_SZ * D1];
__device__ unsigned g_mm[4];

__device__ __forceinline__ unsigned encf(float f) {
    unsigned u = __float_as_uint(f);
    return (u & 0x80000000u) ? ~u : (u | 0x80000000u);
}
__device__ __forceinline__ float decf(unsigned u) {
    u = (u & 0x80000000u) ? (u & 0x7FFFFFFFu) : ~u;
    return __uint_as_float(u);
}
__device__ __forceinline__ unsigned tf32u(float f) {
    unsigned u; asm("cvt.rna.tf32.f32 %0, %1;" : "=r"(u) : "f"(f)); return u;
}
__device__ __forceinline__ float tf32f(float f) { return __uint_as_float(tf32u(f)); }

__device__ __forceinline__ float blkSum(float v, float* sbuf) {
    int lane = threadIdx.x & 31;
#pragma unroll
    for (int o = 16; o; o >>= 1) v += __shfl_xor_sync(0xffffffffu, v, o);
    __syncthreads();
    if (lane == 0) sbuf[threadIdx.x >> 5] = v;
    __syncthreads();
    int nw = blockDim.x >> 5;
    float r = (lane < nw) ? sbuf[lane] : 0.f;
#pragma unroll
    for (int o = 16; o; o >>= 1) r += __shfl_xor_sync(0xffffffffu, r, o);
    return r;
}

// C_part[slab] = A' @ W^T ; MODE0: A'=silu(A), K=lda ; MODE1: A'=legendre(t(A)), K=4*lda
template <int MODE>
__global__ void __launch_bounds__(NT) kal_gemm(
    const float* __restrict__ A, int lda,
    const float* __restrict__ W, long ldw,
    float* __restrict__ Cp, int ldc, int ktiles, int mmOff)
{
    extern __shared__ float smem[];
    float* As = smem;
    float* Bs = smem + 2 * BM * BK;

    const int tid = threadIdx.x, lane = tid & 31, wid = tid >> 5;
    const int wm0 = (wid & 1) * 64, wn0 = (wid >> 1) * 32;
    const int rr = lane >> 2, cc = lane & 3, swz = rr << 2;
    const int ntile = blockIdx.x, mtile = blockIdx.y, slab = blockIdx.z;
    const long kbase = (long)slab * ktiles * BK;

    const int frow = tid >> 1, fcol0 = (tid & 1) * 16, fswz = (frow & 7) << 2;
    const float* wsrc = W + (size_t)(ntile * BN + frow) * ldw + kbase + fcol0;

    const float* asrc;
    float sA = 0.f, sB = 0.f;
    if (MODE == 0) {
        asrc = A + (size_t)(mtile * BM + frow) * lda + kbase + fcol0;
    } else {
        asrc = A + (size_t)(mtile * BM + frow) * lda + (kbase >> 2) + (fcol0 >> 2);
        float xmin = decf(g_mm[mmOff]), xmax = decf(g_mm[mmOff + 1]);
        sA = 2.0f / (xmax - xmin);
        sB = -sA * xmin - 1.0f;
    }

    float4 a4[4];
    float  ax[4];

    auto fillB = [&](int kt, float* bst) {
#pragma unroll
        for (int i = 0; i < 4; i++) {
            float* dst = bst + frow * BK + ((fcol0 + 4 * i) ^ fswz);
            unsigned sa = (unsigned)__cvta_generic_to_shared(dst);
            asm volatile("cp.async.ca.shared.global [%0], [%1], 16;" ::"r"(sa),
                         "l"(wsrc + (size_t)kt * BK + 4 * i));
        }
    };
    auto ldA = [&](int kt) {
        if (MODE == 0) {
#pragma unroll
            for (int i = 0; i < 4; i++)
                a4[i] = *reinterpret_cast<const float4*>(asrc + (size_t)kt * BK + 4 * i);
        } else {
#pragma unroll
            for (int i = 0; i < 4; i++) ax[i] = asrc[kt * 8 + i];
        }
    };
    auto stA = [&](float* ast) {
#pragma unroll
        for (int i = 0; i < 4; i++) {
            float4 v;
            if (MODE == 0) {
                v.x = a4[i].x / (1.0f + __expf(-a4[i].x));
                v.y = a4[i].y / (1.0f + __expf(-a4[i].y));
                v.z = a4[i].z / (1.0f + __expf(-a4[i].z));
                v.w = a4[i].w / (1.0f + __expf(-a4[i].w));
            } else {
                float t = fmaf(ax[i], sA, sB), t2 = t * t;
                v.x = 1.0f; v.y = t;
                v.z = fmaf(1.5f, t2, -0.5f);
                v.w = t * fmaf(2.5f, t2, -1.5f);
            }
            v.x = tf32f(v.x); v.y = tf32f(v.y); v.z = tf32f(v.z); v.w = tf32f(v.w);
            *reinterpret_cast<float4*>(ast + frow * BK + ((fcol0 + 4 * i) ^ fswz)) = v;
        }
    };

    float acc[4][4][4] = {};

    auto compute = [&](const float* Ast, const float* Bst) {
#pragma unroll
        for (int kc = 0; kc < 4; kc++) {
            const int c0 = (kc * 8 + cc) ^ swz;
            const int c1 = (kc * 8 + cc + 4) ^ swz;
            unsigned af[4][4];
#pragma unroll
            for (int i = 0; i < 4; i++) {
                int row = wm0 + i * 16 + rr;
                af[i][0] = __float_as_uint(Ast[row * BK + c0]);
                af[i][1] = __float_as_uint(Ast[(row + 8) * BK + c0]);
                af[i][2] = __float_as_uint(Ast[row * BK + c1]);
                af[i][3] = __float_as_uint(Ast[(row + 8) * BK + c1]);
            }
#pragma unroll
            for (int j = 0; j < 4; j++) {
                int n = wn0 + j * 8 + rr;
                unsigned b0 = tf32u(Bst[n * BK + c0]);
                unsigned b1 = tf32u(Bst[n * BK + c1]);
#pragma unroll
                for (int i = 0; i < 4; i++) {
                    asm volatile(
                        "mma.sync.aligned.m16n8k8.row.col.f32.tf32.tf32.f32 "
                        "{%0,%1,%2,%3}, {%4,%5,%6,%7}, {%8,%9}, {%0,%1,%2,%3};"
                        : "+f"(acc[i][j][0]), "+f"(acc[i][j][1]),
                          "+f"(acc[i][j][2]), "+f"(acc[i][j][3])
                        : "r"(af[i][0]), "r"(af[i][1]), "r"(af[i][2]), "r"(af[i][3]),
                          "r"(b0), "r"(b1));
                }
            }
        }
    };

    ldA(0);
    fillB(0, Bs);
    asm volatile("cp.async.commit_group;");
    stA(As);
    asm volatile("cp.async.wait_group 0;");
    __syncthreads();

    for (int kt = 0; kt < ktiles; kt++) {
        const int cur = kt & 1;
        float* Ac = As + cur * BM * BK;
        float* Bc = Bs + cur * BM * BK;
        float* An = As + (cur ^ 1) * BM * BK;
        const bool more = (kt + 1) < ktiles;
        if (more) {
            fillB(kt + 1, Bs + (cur ^ 1) * BM * BK);
            asm volatile("cp.async.commit_group;");
            ldA(kt + 1);
        }
        compute(Ac, Bc);
        if (more) {
            stA(An);
            asm volatile("cp.async.wait_group 0;");
        }
        __syncthreads();
    }

    const int c2 = cc * 2;
#pragma unroll
    for (int i = 0; i < 4; i++) {
        int row = mtile * BM + wm0 + i * 16 + rr;
#pragma unroll
        for (int j = 0; j < 4; j++) {
            int col = ntile * BN + wn0 + j * 8 + c2;
            size_t o = ((size_t)slab * B_SZ + row) * (size_t)ldc + col;
            *reinterpret_cast<float2*>(&Cp[o]) = make_float2(acc[i][j][0], acc[i][j][1]);
            *reinterpret_cast<float2*>(&Cp[o + 8 * (size_t)ldc]) =
                make_float2(acc[i][j][2], acc[i][j][3]);
        }
    }
}

__global__ void k_init() {
    g_mm[0] = encf(FLT_MAX); g_mm[1] = encf(-FLT_MAX);
    g_mm[2] = encf(FLT_MAX); g_mm[3] = encf(-FLT_MAX);
}

__global__ void k_minmax(const float4* __restrict__ x, int n4) {
    float lo = FLT_MAX, hi = -FLT_MAX;
    for (int i = blockIdx.x * blockDim.x + threadIdx.x; i < n4; i += gridDim.x * blockDim.x) {
        float4 v = x[i];
        lo = fminf(lo, fminf(fminf(v.x, v.y), fminf(v.z, v.w)));
        hi = fmaxf(hi, fmaxf(fmaxf(v.x, v.y), fmaxf(v.z, v.w)));
    }
#pragma unroll
    for (int o = 16; o; o >>= 1) {
        lo = fminf(lo, __shfl_xor_sync(0xffffffffu, lo, o));
        hi = fmaxf(hi, __shfl_xor_sync(0xffffffffu, hi, o));
    }
    __shared__ float slo[8], shi[8];
    if ((threadIdx.x & 31) == 0) { slo[threadIdx.x >> 5] = lo; shi[threadIdx.x >> 5] = hi; }
    __syncthreads();
    if (threadIdx.x == 0) {
#pragma unroll
        for (int w = 1; w < 8; w++) { lo = fminf(lo, slo[w]); hi = fmaxf(hi, shi[w]); }
        atomicMin(&g_mm[0], encf(lo));
        atomicMax(&g_mm[1], encf(hi));
    }
}

__global__ void k_reduce_ln0(const float* __restrict__ part,
                             const float* __restrict__ gamma,
                             const float* __restrict__ beta) {
    const int b = blockIdx.x, tid = threadIdx.x;
    float h[4];
#pragma unroll
    for (int q = 0; q < 4; q++) {
        int n = tid + q * 256;
        float acc = 0.f;
        for (int s = 0; s < S0_TOT; s++) acc += part[((size_t)s * B_SZ + b) * D1 + n];
        h[q] = acc;
    }
    __shared__ float sbuf[32];
    float mean = blkSum(h[0] + h[1] + h[2] + h[3], sbuf) * (1.0f / D1);
    float s2 = 0.f;
#pragma unroll
    for (int q = 0; q < 4; q++) { float d = h[q] - mean; s2 += d * d; }
    float inv = rsqrtf(blkSum(s2, sbuf) * (1.0f / D1) + 1e-5f);
    float lo = FLT_MAX, hi = -FLT_MAX;
#pragma unroll
    for (int q = 0; q < 4; q++) {
        int n = tid + q * 256;
        float y = (h[q] - mean) * inv * gamma[n] + beta[n];
        float a = y / (1.0f + expf(-y));
        g_h0[b * D1 + n] = a;
        lo = fminf(lo, a); hi = fmaxf(hi, a);
    }
#pragma unroll
    for (int o = 16; o; o >>= 1) {
        lo = fminf(lo, __shfl_xor_sync(0xffffffffu, lo, o));
        hi = fmaxf(hi, __shfl_xor_sync(0xffffffffu, hi, o));
    }
    __shared__ float slo[8], shi[8];
    if ((tid & 31) == 0) { slo[tid >> 5] = lo; shi[tid >> 5] = hi; }
    __syncthreads();
    if (tid == 0) {
#pragma unroll
        for (int w = 1; w < 8; w++) { lo = fminf(lo, slo[w]); hi = fmaxf(hi, shi[w]); }
        atomicMin(&g_mm[2], encf(lo));
        atomicMax(&g_mm[3], encf(hi));
    }
}

__global__ void k_reduce_ln1(const float* __restrict__ part,
                             const float* __restrict__ gamma,
                             const float* __restrict__ beta,
                             const float* __restrict__ ow,
                             const float* __restrict__ ob,
                             float* __restrict__ out) {
    const int b = blockIdx.x, tid = threadIdx.x;  // 128 threads
    float acc = 0.f;
    for (int s = 0; s < SL1_TOT; s++) acc += part[((size_t)s * B_SZ + b) * D2 + tid];
    __shared__ float sbuf[32];
    float mean = blkSum(acc, sbuf) * (1.0f / D2);
    float d = acc - mean;
    float var = blkSum(d * d, sbuf) * (1.0f / D2);
    float y = d * rsqrtf(var + 1e-5f) * gamma[tid] + beta[tid];
    float a = y / (1.0f + expf(-y));
    float l0 = blkSum(a * ow[tid], sbuf);
    float l1 = blkSum(a * ow[128 + tid], sbuf);
    if (tid == 0) {
        l0 += ob[0]; l1 += ob[1];
        float m = fmaxf(l0, l1);
        float e0 = expf(l0 - m), e1 = expf(l1 - m);
        float inv = 1.f / (e0 + e1);
        out[b * 2 + 0] = e0 * inv;
        out[b * 2 + 1] = e1 * inv;
    }
}

extern "C" void kernel_launch(void* const* d_in, const int* in_sizes, int n_in,
                              void* d_out, int out_size) {
    (void)in_sizes; (void)n_in; (void)out_size;
    const float* x       = (const float*)d_in[0];
    const float* base_w0 = (const float*)d_in[1];
    const float* poly_w0 = (const float*)d_in[2];
    const float* ln_g0   = (const float*)d_in[3];
    const float* ln_b0   = (const float*)d_in[4];
    const float* base_w1 = (const float*)d_in[5];
    const float* poly_w1 = (const float*)d_in[6];
    const float* ln_g1   = (const float*)d_in[7];
    const float* ln_b1   = (const float*)d_in[8];
    const float* out_w   = (const float*)d_in[9];
    const float* out_b   = (const float*)d_in[10];
    float* out = (float*)d_out;

    float *part0, *part1, *h0;
    cudaGetSymbolAddress((void**)&part0, g_part0);
    cudaGetSymbolAddress((void**)&part1, g_part1);
    cudaGetSymbolAddress((void**)&h0, g_h0);

    const int SMEM = 4 * BM * BK * (int)sizeof(float);
    cudaFuncSetAttribute(kal_gemm<0>, cudaFuncAttributeMaxDynamicSharedMemorySize, SMEM);
    cudaFuncSetAttribute(kal_gemm<1>, cudaFuncAttributeMaxDynamicSharedMemorySize, SMEM);

    k_init<<<1, 1>>>();
    k_minmax<<<1024, 256>>>((const float4*)x, B_SZ * D0 / 4);

    kal_gemm<0><<<dim3(8, 2, S1), NT, SMEM>>>(x, D0, base_w0, D0, part0, D1, KT0, 0);
    kal_gemm<1><<<dim3(8, 2, S2), NT, SMEM>>>(x, D0, poly_w0, (long)D0 * 4,
                                              part0 + (size_t)S1 * B_SZ * D1, D1, KT0, 0);
    k_reduce_ln0<<<B_SZ, 256>>>(part0, ln_g0, ln_b0);

    kal_gemm<0><<<dim3(1, 2, S3), NT, SMEM>>>(h0, D1, base_w1, D1, part1, D2, KT3, 2);
    kal_gemm<1><<<dim3(1, 2, S4), NT, SMEM>>>(h0, D1, poly_w1, (long)D1 * 4,
                                              part1 + (size_t)S3 * B_SZ * D2, D2, KT4, 2);
    k_reduce_ln1<<<B_SZ, 128>>>(part1, ln_g1, ln_b1, out_w, out_b, out);
}